// round 1
// baseline (speedup 1.0000x reference)
#include <cuda_runtime.h>
#include <math.h>

#define SEQ   4096
#define EMB   768
#define HEADS 12
#define HD    64

// ---------------- scratch (static device globals, no runtime alloc) ----------------
__device__ float g_Q[SEQ * EMB];
__device__ float g_K[SEQ * EMB];
__device__ float g_V[SEQ * EMB];
__device__ float g_CTX[SEQ * EMB];

// ---------------- GEMM: C[M,N] = A[M,K] @ B[K,N] + bias[N] ----------------
#define GBM 64
#define GBN 64
#define GBK 16

__global__ __launch_bounds__(128) void gemm_bias_kernel(
    const float* __restrict__ A, const float* __restrict__ B,
    const float* __restrict__ bias, float* __restrict__ C,
    int M, int N, int K)
{
    __shared__ float As[GBK][GBM + 4];   // transposed A tile, stride 68 floats (16B aligned rows)
    __shared__ float Bs[GBK][GBN];

    const int tid = threadIdx.x;
    const int m0 = blockIdx.y * GBM;
    const int n0 = blockIdx.x * GBN;
    const int t_r = tid >> 4;   // 0..7  -> rows t_r*8 .. +8
    const int t_c = tid & 15;   // 0..15 -> cols t_c*4 .. +4

    float acc[8][4];
#pragma unroll
    for (int i = 0; i < 8; ++i)
#pragma unroll
        for (int j = 0; j < 4; ++j) acc[i][j] = 0.f;

    for (int k0 = 0; k0 < K; k0 += GBK) {
        // A tile: 64x16, stored transposed As[k][m]
#pragma unroll
        for (int i = 0; i < 2; ++i) {
            int f  = i * 128 + tid;       // float4 index, 256 total
            int m  = f >> 2;              // 0..63
            int k4 = f & 3;               // 0..3
            float4 v = *(const float4*)(A + (size_t)(m0 + m) * K + k0 + k4 * 4);
            As[k4 * 4 + 0][m] = v.x;
            As[k4 * 4 + 1][m] = v.y;
            As[k4 * 4 + 2][m] = v.z;
            As[k4 * 4 + 3][m] = v.w;
        }
        // B tile: 16x64 direct
#pragma unroll
        for (int i = 0; i < 2; ++i) {
            int f  = i * 128 + tid;
            int k  = f >> 4;
            int n4 = f & 15;
            *(float4*)(&Bs[k][n4 * 4]) =
                *(const float4*)(B + (size_t)(k0 + k) * N + n0 + n4 * 4);
        }
        __syncthreads();

#pragma unroll
        for (int kk = 0; kk < GBK; ++kk) {
            float a[8], b[4];
            *(float4*)(a)     = *(const float4*)(&As[kk][t_r * 8]);
            *(float4*)(a + 4) = *(const float4*)(&As[kk][t_r * 8 + 4]);
            *(float4*)(b)     = *(const float4*)(&Bs[kk][t_c * 4]);
#pragma unroll
            for (int i = 0; i < 8; ++i)
#pragma unroll
                for (int j = 0; j < 4; ++j)
                    acc[i][j] += a[i] * b[j];
        }
        __syncthreads();
    }

    float4 bb = *(const float4*)(bias + n0 + t_c * 4);
#pragma unroll
    for (int i = 0; i < 8; ++i) {
        float4 c;
        c.x = acc[i][0] + bb.x;
        c.y = acc[i][1] + bb.y;
        c.z = acc[i][2] + bb.z;
        c.w = acc[i][3] + bb.w;
        *(float4*)(C + (size_t)(m0 + t_r * 8 + i) * N + n0 + t_c * 4) = c;
    }
}

// ---------------- causal flash attention, fp32 ----------------
// grid: (32, HEADS), block: 64 threads. Each block processes q-tiles (x) and (63-x)
// sequentially -> identical work per block (130 KV tiles of 32).
#define ABM 64
#define ABN 32
#define NEG_BIG (-1e30f)

__global__ __launch_bounds__(64) void attn_kernel(
    const float* __restrict__ Q, const float* __restrict__ K,
    const float* __restrict__ V, float* __restrict__ CTX)
{
    __shared__ float Qs[ABM][68];     // per-row float4 stride 17 -> conflict-free
    __shared__ float Ks[ABN][HD];
    __shared__ float Vs[ABN][HD];

    const int h   = blockIdx.y;
    const int tid = threadIdx.x;

#pragma unroll 1
    for (int half = 0; half < 2; ++half) {
        const int qt = half ? (63 - blockIdx.x) : blockIdx.x;
        const int r  = qt * ABM + tid;      // this thread's global q row

        __syncthreads();   // previous half's reads of Qs are done
        // stage Q tile (coalesced)
#pragma unroll
        for (int i = 0; i < 16; ++i) {
            int f   = i * 64 + tid;          // 1024 float4
            int row = f >> 4;
            int d4  = f & 15;
            *(float4*)(&Qs[row][d4 * 4]) =
                *(const float4*)(Q + (size_t)(qt * ABM + row) * EMB + h * HD + d4 * 4);
        }
        __syncthreads();

        float o[HD];
#pragma unroll
        for (int d = 0; d < HD; ++d) o[d] = 0.f;
        float mval = NEG_BIG, l = 0.f;

        const int ntiles = 2 * qt + 2;      // covers kv rows [0, qt*64+64)
#pragma unroll 1
        for (int t = 0; t < ntiles; ++t) {
            const int kbase = t * ABN;
            __syncthreads();
#pragma unroll
            for (int i = 0; i < 8; ++i) {
                int f   = i * 64 + tid;      // 512 float4 per tile
                int row = f >> 4;
                int d4  = f & 15;
                *(float4*)(&Ks[row][d4 * 4]) =
                    *(const float4*)(K + (size_t)(kbase + row) * EMB + h * HD + d4 * 4);
                *(float4*)(&Vs[row][d4 * 4]) =
                    *(const float4*)(V + (size_t)(kbase + row) * EMB + h * HD + d4 * 4);
            }
            __syncthreads();

            // scores: 32 independent accumulator chains (j-inner)
            float p[ABN];
#pragma unroll
            for (int j = 0; j < ABN; ++j) p[j] = 0.f;
#pragma unroll 1
            for (int d4 = 0; d4 < 16; ++d4) {
                float4 qv = *(const float4*)(&Qs[tid][d4 * 4]);
#pragma unroll
                for (int j = 0; j < ABN; ++j) {
                    float4 kv = *(const float4*)(&Ks[j][d4 * 4]);   // warp broadcast
                    p[j] += qv.x * kv.x + qv.y * kv.y + qv.z * kv.z + qv.w * kv.w;
                }
            }

            // causal mask + online softmax (scale 1/sqrt(64) folded into exp)
            float tmax = NEG_BIG;
#pragma unroll
            for (int j = 0; j < ABN; ++j) {
                if (kbase + j > r) p[j] = NEG_BIG;
                tmax = fmaxf(tmax, p[j]);
            }
            const float mnew  = fmaxf(mval, tmax);
            const float alpha = __expf((mval - mnew) * 0.125f);
            float psum = 0.f;
#pragma unroll
            for (int j = 0; j < ABN; ++j) {
                p[j] = __expf((p[j] - mnew) * 0.125f);
                psum += p[j];
            }
            l = l * alpha + psum;
            mval = mnew;
#pragma unroll
            for (int d = 0; d < HD; ++d) o[d] *= alpha;

            // PV accumulate
#pragma unroll
            for (int j = 0; j < ABN; ++j) {
                const float pj = p[j];
#pragma unroll
                for (int d4 = 0; d4 < 16; ++d4) {
                    float4 v = *(const float4*)(&Vs[j][d4 * 4]);    // warp broadcast
                    o[d4 * 4 + 0] += pj * v.x;
                    o[d4 * 4 + 1] += pj * v.y;
                    o[d4 * 4 + 2] += pj * v.z;
                    o[d4 * 4 + 3] += pj * v.w;
                }
            }
        }

        const float inv = 1.f / l;
#pragma unroll
        for (int d4 = 0; d4 < 16; ++d4) {
            float4 c;
            c.x = o[d4 * 4 + 0] * inv;
            c.y = o[d4 * 4 + 1] * inv;
            c.z = o[d4 * 4 + 2] * inv;
            c.w = o[d4 * 4 + 3] * inv;
            *(float4*)(CTX + (size_t)r * EMB + h * HD + d4 * 4) = c;
        }
    }
}

// ---------------- launch ----------------
extern "C" void kernel_launch(void* const* d_in, const int* in_sizes, int n_in,
                              void* d_out, int out_size)
{
    const float* x  = (const float*)d_in[0];
    const float* wq = (const float*)d_in[1];
    const float* bq = (const float*)d_in[2];
    const float* wk = (const float*)d_in[3];
    const float* bk = (const float*)d_in[4];
    const float* wv = (const float*)d_in[5];
    const float* bv = (const float*)d_in[6];
    const float* wo = (const float*)d_in[7];
    const float* bo = (const float*)d_in[8];
    float* out = (float*)d_out;

    float *Qp, *Kp, *Vp, *Cp;
    cudaGetSymbolAddress((void**)&Qp, g_Q);
    cudaGetSymbolAddress((void**)&Kp, g_K);
    cudaGetSymbolAddress((void**)&Vp, g_V);
    cudaGetSymbolAddress((void**)&Cp, g_CTX);

    const int M = SEQ, N = EMB, K = EMB;
    dim3 ggrid(N / GBN, M / GBM);   // (12, 64)
    dim3 gblk(128);

    gemm_bias_kernel<<<ggrid, gblk>>>(x, wq, bq, Qp, M, N, K);
    gemm_bias_kernel<<<ggrid, gblk>>>(x, wk, bk, Kp, M, N, K);
    gemm_bias_kernel<<<ggrid, gblk>>>(x, wv, bv, Vp, M, N, K);

    dim3 agrid(32, HEADS);
    attn_kernel<<<agrid, 64>>>(Qp, Kp, Vp, Cp);

    gemm_bias_kernel<<<ggrid, gblk>>>(Cp, wo, bo, out, M, N, K);
}